// round 3
// baseline (speedup 1.0000x reference)
#include <cuda_runtime.h>

// ---------------------------------------------------------------------------
// GAT fused kernel set.
// Shapes: B=32, N=14, IN_F=OUT_F=1024, H=4, F = N*OUT_F = 14336.
//   k1: per (h,b) block: Wh = x@W, Wh1/Wh2 dots, 14x14 masked softmax(axis=n),
//       h_prime = att@Wh  -> g_hp
//   k2: out_part[h,ks] = h_prime @ fc_w^T (k-split)        -> g_part
//   k3: reduce partials + fc_b, log_softmax over OUT_F     -> d_out
// ---------------------------------------------------------------------------

#define NEGC -9e15f

__device__ __forceinline__ float2 ffma2(float2 a, float2 b, float2 c) {
    float2 d;
    asm("fma.rn.f32x2 %0, %1, %2, %3;"
        : "=l"(*reinterpret_cast<unsigned long long*>(&d))
        : "l"(*reinterpret_cast<unsigned long long*>(&a)),
          "l"(*reinterpret_cast<unsigned long long*>(&b)),
          "l"(*reinterpret_cast<unsigned long long*>(&c)));
    return d;
}

// scratch (allocation-free rule: __device__ globals)
__device__ float g_hp[4 * 32 * 14 * 1024];     // h_prime  (h,b,f) 7.34 MB
__device__ float g_part[64 * 32 * 1024];       // partials (h*16+ks, b, o) 8 MB

// ---------------------------------------------------------------------------
// Kernel 1: one block per (h,b). 256 threads, thread owns 4 output columns.
// dynamic smem: 14336 floats (x transposed, later reused for Wh).
// ---------------------------------------------------------------------------
__global__ __launch_bounds__(256, 1) void k1(
    const float* __restrict__ x, const float* __restrict__ adj,
    const float* __restrict__ W, const float* __restrict__ a)
{
    extern __shared__ float s_x[];              // [i*14 + n] then Wh [n*1024+c]
    __shared__ float s_att[14 * 16];            // att stored [m*16 + n]
    __shared__ float s_wh1[14], s_wh2[14];

    const int tid = threadIdx.x;
    const int hb  = blockIdx.x;                 // h*32 + b
    const int b   = hb & 31;
    const int c0  = tid * 4;

    // ---- load x[b] transposed into smem: s_x[i*14 + n] ----
    const float* xb = x + (size_t)b * 14336;
    for (int idx = tid; idx < 14336; idx += 256) {
        int n = idx >> 10, i = idx & 1023;
        s_x[i * 14 + n] = xb[idx];
    }
    __syncthreads();

    // ---- GEMM: Wh[n][c0..c0+3] accumulated as 7 n-pairs x 4 cols (f32x2) ----
    const float4* W4 = (const float4*)(W + ((size_t)hb << 20));
    float2 acc[7][4];
    #pragma unroll
    for (int p = 0; p < 7; p++)
        #pragma unroll
        for (int c = 0; c < 4; c++) acc[p][c] = make_float2(0.f, 0.f);

    float4 wc[4];
    #pragma unroll
    for (int u = 0; u < 4; u++) wc[u] = W4[u * 256 + tid];

    #pragma unroll 1
    for (int k = 0; k < 1024; k += 4) {
        float4 wn[4];
        if (k + 4 < 1024) {
            #pragma unroll
            for (int u = 0; u < 4; u++) wn[u] = W4[(size_t)(k + 4 + u) * 256 + tid];
        }
        #pragma unroll
        for (int u = 0; u < 4; u++) {
            const int kk = k + u;
            float2 xv[7];
            #pragma unroll
            for (int p = 0; p < 7; p++)
                xv[p] = *(const float2*)&s_x[kk * 14 + 2 * p];
            float2 s0 = make_float2(wc[u].x, wc[u].x);
            float2 s1 = make_float2(wc[u].y, wc[u].y);
            float2 s2 = make_float2(wc[u].z, wc[u].z);
            float2 s3 = make_float2(wc[u].w, wc[u].w);
            #pragma unroll
            for (int p = 0; p < 7; p++) {
                acc[p][0] = ffma2(xv[p], s0, acc[p][0]);
                acc[p][1] = ffma2(xv[p], s1, acc[p][1]);
                acc[p][2] = ffma2(xv[p], s2, acc[p][2]);
                acc[p][3] = ffma2(xv[p], s3, acc[p][3]);
            }
        }
        #pragma unroll
        for (int u = 0; u < 4; u++) wc[u] = wn[u];
    }

    __syncthreads();   // all threads done reading x from s_x
    // ---- store Wh into smem, layout [n*1024 + c] ----
    #pragma unroll
    for (int p = 0; p < 7; p++) {
        *(float4*)&s_x[(2 * p) * 1024 + c0] =
            make_float4(acc[p][0].x, acc[p][1].x, acc[p][2].x, acc[p][3].x);
        *(float4*)&s_x[(2 * p + 1) * 1024 + c0] =
            make_float4(acc[p][0].y, acc[p][1].y, acc[p][2].y, acc[p][3].y);
    }
    __syncthreads();

    // ---- Wh1[n] = Wh[n]·a1, Wh2[n] = Wh[n]·a2 (warp per row) ----
    const int wid = tid >> 5, lane = tid & 31;
    const float* av = a + (size_t)hb * 2048;
    for (int n = wid; n < 14; n += 8) {
        float s1 = 0.f, s2 = 0.f;
        for (int c = lane; c < 1024; c += 32) {
            float v = s_x[n * 1024 + c];
            s1 = fmaf(v, av[c], s1);
            s2 = fmaf(v, av[1024 + c], s2);
        }
        #pragma unroll
        for (int off = 16; off > 0; off >>= 1) {
            s1 += __shfl_down_sync(0xFFFFFFFFu, s1, off);
            s2 += __shfl_down_sync(0xFFFFFFFFu, s2, off);
        }
        if (lane == 0) { s_wh1[n] = s1; s_wh2[n] = s2; }
    }
    __syncthreads();

    // ---- e = leaky_relu(Wh1[n]+Wh2[m]); mask by adj; store [m][n] ----
    if (tid < 196) {
        int n = tid / 14, m = tid - n * 14;
        float e = s_wh1[n] + s_wh2[m];
        e = (e > 0.f) ? e : 0.2f * e;
        float ad = adj[b * 196 + n * 14 + m];
        s_att[m * 16 + n] = (ad > 0.f) ? e : NEGC;
    }
    __syncthreads();

    // ---- softmax over n (axis=2), one thread per m ----
    if (tid < 14) {
        const int m = tid;
        float mx = -3.4e38f;
        float ev[14];
        #pragma unroll
        for (int n = 0; n < 14; n++) mx = fmaxf(mx, s_att[m * 16 + n]);
        float s = 0.f;
        #pragma unroll
        for (int n = 0; n < 14; n++) { ev[n] = expf(s_att[m * 16 + n] - mx); s += ev[n]; }
        float inv = 1.f / s;
        #pragma unroll
        for (int n = 0; n < 14; n++) s_att[m * 16 + n] = ev[n] * inv;
    }
    __syncthreads();

    // ---- h_prime[n][c] = sum_m att[n][m] * Wh[m][c] ----
    float2 hp[7][4];
    #pragma unroll
    for (int p = 0; p < 7; p++)
        #pragma unroll
        for (int c = 0; c < 4; c++) hp[p][c] = make_float2(0.f, 0.f);

    #pragma unroll 1
    for (int m = 0; m < 14; m++) {
        float4 wm = *(const float4*)&s_x[m * 1024 + c0];
        float2 t0 = make_float2(wm.x, wm.x);
        float2 t1 = make_float2(wm.y, wm.y);
        float2 t2 = make_float2(wm.z, wm.z);
        float2 t3 = make_float2(wm.w, wm.w);
        #pragma unroll
        for (int p = 0; p < 7; p++) {
            float2 at = *(const float2*)&s_att[m * 16 + 2 * p];
            hp[p][0] = ffma2(at, t0, hp[p][0]);
            hp[p][1] = ffma2(at, t1, hp[p][1]);
            hp[p][2] = ffma2(at, t2, hp[p][2]);
            hp[p][3] = ffma2(at, t3, hp[p][3]);
        }
    }
    float* hpg = g_hp + (size_t)hb * 14336;
    #pragma unroll
    for (int p = 0; p < 7; p++) {
        *(float4*)&hpg[(2 * p) * 1024 + c0] =
            make_float4(hp[p][0].x, hp[p][1].x, hp[p][2].x, hp[p][3].x);
        *(float4*)&hpg[(2 * p + 1) * 1024 + c0] =
            make_float4(hp[p][0].y, hp[p][1].y, hp[p][2].y, hp[p][3].y);
    }
}

// ---------------------------------------------------------------------------
// Kernel 2: out_part = h_prime @ fc_w^T, k-split by 16 (896 f each).
// grid (ks=16, ot=2, h=4), 256 threads; thread owns 2 o's, all 32 b (b-pairs).
// ---------------------------------------------------------------------------
__global__ __launch_bounds__(256, 1) void k2(const float* __restrict__ fcw)
{
    __shared__ float s_hp[128 * 34];            // [fl*34 + b]

    const int tid = threadIdx.x;
    const int ks  = blockIdx.x;                 // 0..15
    const int ot  = blockIdx.y;                 // 0..1
    const int h   = blockIdx.z;                 // 0..3
    const int o0  = ot * 512 + tid * 2;
    const int fbase = ks * 896;

    const float* w0 = fcw + ((size_t)(h * 1024 + o0)) * 14336 + fbase;
    const float* w1 = w0 + 14336;

    float2 a0[16], a1v[16];
    #pragma unroll
    for (int bp = 0; bp < 16; bp++) { a0[bp] = make_float2(0.f, 0.f); a1v[bp] = make_float2(0.f, 0.f); }

    const int lb = tid >> 3;                    // 0..31 (b for loading)
    const int lf = (tid & 7) * 16;              // f offset within tile
    const float* hrow = g_hp + ((size_t)(h * 32 + lb)) * 14336 + fbase + lf;

    #pragma unroll 1
    for (int t = 0; t < 7; t++) {
        __syncthreads();                        // previous compute done
        float4 v[4];
        #pragma unroll
        for (int q = 0; q < 4; q++) v[q] = *(const float4*)(hrow + t * 128 + q * 4);
        #pragma unroll
        for (int q = 0; q < 4; q++) {
            s_hp[(lf + q * 4 + 0) * 34 + lb] = v[q].x;
            s_hp[(lf + q * 4 + 1) * 34 + lb] = v[q].y;
            s_hp[(lf + q * 4 + 2) * 34 + lb] = v[q].z;
            s_hp[(lf + q * 4 + 3) * 34 + lb] = v[q].w;
        }
        __syncthreads();

        const float* wt0 = w0 + t * 128;
        const float* wt1 = w1 + t * 128;
        float4 wa = *(const float4*)(wt0);
        float4 wb = *(const float4*)(wt1);
        #pragma unroll 1
        for (int g = 0; g < 32; g++) {
            float4 na, nb;
            if (g < 31) {
                na = *(const float4*)(wt0 + (g + 1) * 4);
                nb = *(const float4*)(wt1 + (g + 1) * 4);
            }
            float wva[4] = {wa.x, wa.y, wa.z, wa.w};
            float wvb[4] = {wb.x, wb.y, wb.z, wb.w};
            #pragma unroll
            for (int j = 0; j < 4; j++) {
                float2 sa = make_float2(wva[j], wva[j]);
                float2 sb = make_float2(wvb[j], wvb[j]);
                const float* hb_ = &s_hp[(g * 4 + j) * 34];
                #pragma unroll
                for (int bp = 0; bp < 16; bp++) {
                    float2 hv = *(const float2*)(hb_ + 2 * bp);
                    a0[bp]  = ffma2(hv, sa, a0[bp]);
                    a1v[bp] = ffma2(hv, sb, a1v[bp]);
                }
            }
            wa = na; wb = nb;
        }
    }

    float* dst = g_part + ((size_t)(h * 16 + ks)) * 32768 + o0;
    #pragma unroll
    for (int bp = 0; bp < 16; bp++) {
        *(float2*)(dst + (size_t)(2 * bp) * 1024)     = make_float2(a0[bp].x, a1v[bp].x);
        *(float2*)(dst + (size_t)(2 * bp + 1) * 1024) = make_float2(a0[bp].y, a1v[bp].y);
    }
}

// ---------------------------------------------------------------------------
// Kernel 3: reduce 64 partials + fc_b, then log_softmax over OUT_F per b.
// ---------------------------------------------------------------------------
__global__ __launch_bounds__(256, 1) void k3(const float* __restrict__ fcb,
                                             float* __restrict__ out)
{
    __shared__ float red[256];
    const int b = blockIdx.x, tid = threadIdx.x;

    float v[4];
    #pragma unroll
    for (int j = 0; j < 4; j++) {
        int o = tid + j * 256;
        float s = 0.f;
        #pragma unroll 4
        for (int pb = 0; pb < 64; pb++)
            s += g_part[(size_t)pb * 32768 + b * 1024 + o];
        #pragma unroll
        for (int hh = 0; hh < 4; hh++) s += fcb[hh * 1024 + o];
        v[j] = s;
    }

    float mx = fmaxf(fmaxf(v[0], v[1]), fmaxf(v[2], v[3]));
    red[tid] = mx; __syncthreads();
    for (int st = 128; st > 0; st >>= 1) {
        if (tid < st) red[tid] = fmaxf(red[tid], red[tid + st]);
        __syncthreads();
    }
    mx = red[0]; __syncthreads();

    float s = 0.f;
    #pragma unroll
    for (int j = 0; j < 4; j++) s += expf(v[j] - mx);
    red[tid] = s; __syncthreads();
    for (int st = 128; st > 0; st >>= 1) {
        if (tid < st) red[tid] += red[tid + st];
        __syncthreads();
    }
    float lse = mx + logf(red[0]);

    #pragma unroll
    for (int j = 0; j < 4; j++)
        out[b * 1024 + tid + j * 256] = v[j] - lse;
}

// ---------------------------------------------------------------------------
extern "C" void kernel_launch(void* const* d_in, const int* in_sizes, int n_in,
                              void* d_out, int out_size)
{
    // identify inputs by element count (robust to ordering)
    const float *x = nullptr, *adj = nullptr, *W = nullptr, *a = nullptr,
                *fcw = nullptr, *fcb = nullptr;
    for (int i = 0; i < n_in; i++) {
        switch (in_sizes[i]) {
            case 32 * 14 * 1024:        x   = (const float*)d_in[i]; break;
            case 32 * 14 * 14:          adj = (const float*)d_in[i]; break;
            case 4 * 32 * 1024 * 1024:  W   = (const float*)d_in[i]; break;
            case 4 * 32 * 2048:         a   = (const float*)d_in[i]; break;
            case 4 * 1024 * 14336:      fcw = (const float*)d_in[i]; break;
            case 4 * 1024:              fcb = (const float*)d_in[i]; break;
            default: break;
        }
    }
    float* out = (float*)d_out;

    cudaFuncSetAttribute(k1, cudaFuncAttributeMaxDynamicSharedMemorySize, 57344);

    k1<<<128, 256, 57344>>>(x, adj, W, a);
    k2<<<dim3(16, 2, 4), 256>>>(fcw);
    k3<<<32, 256>>>(fcb, out);
}

// round 5
// speedup vs baseline: 1.0903x; 1.0903x over previous
#include <cuda_runtime.h>

// ---------------------------------------------------------------------------
// GAT, B=32 N=14 IN=OUT=1024 H=4.
//  k1 : Wh partial GEMM (k-split by 2), pure streaming GEMM, 256 CTAs.
//  k1b: sum partials + a-dots + masked softmax + h_prime (register resident).
//  k2 : out partials = h_prime @ fc_w^T, smem-tiled GEMM, 256 CTAs.
//  k3 : reduce 64 partials + bias + log_softmax.
// ---------------------------------------------------------------------------

#define NEGC -9e15f

__device__ __forceinline__ float2 ffma2(float2 a, float2 b, float2 c) {
    float2 d;
    asm("fma.rn.f32x2 %0, %1, %2, %3;"
        : "=l"(*reinterpret_cast<unsigned long long*>(&d))
        : "l"(*reinterpret_cast<unsigned long long*>(&a)),
          "l"(*reinterpret_cast<unsigned long long*>(&b)),
          "l"(*reinterpret_cast<unsigned long long*>(&c)));
    return d;
}

// scratch
__device__ float g_whp[2][128 * 14 * 1024];    // Wh k-partials, 2 x 7.34MB
__device__ float g_hp[128 * 14 * 1024];        // h_prime (hb, n, c)
__device__ float g_part[64 * 32 * 1024];       // out partials (h*16+ks, b, o)

// ---------------------------------------------------------------------------
// k1: grid 256 = (hb 128) x (khalf 2). 256 threads, thread owns 4 cols.
// Computes partial Wh[n][c] over k-range [kh*512, kh*512+512).
// ---------------------------------------------------------------------------
__global__ __launch_bounds__(256, 2) void k1(
    const float* __restrict__ x, const float* __restrict__ W)
{
    __shared__ float s_x[512 * 16];             // x[k-local][n], stride 16

    const int tid = threadIdx.x;
    const int hb  = blockIdx.x >> 1;
    const int kh  = blockIdx.x & 1;
    const int b   = hb & 31;
    const int k0  = kh * 512;
    const int c0  = tid * 4;

    // stage x[b][n][k0..k0+511] transposed: s_x[ii*16 + n]
    const float* xb = x + (size_t)b * 14336 + k0;
    for (int idx = tid; idx < 14 * 512; idx += 256) {
        int n = idx >> 9, ii = idx & 511;
        s_x[ii * 16 + n] = xb[n * 1024 + ii];
    }
    __syncthreads();

    const float4* W4 = (const float4*)(W + ((size_t)hb << 20) + ((size_t)k0 << 10));

    float2 acc[7][4];
    #pragma unroll
    for (int p = 0; p < 7; p++)
        #pragma unroll
        for (int c = 0; c < 4; c++) acc[p][c] = make_float2(0.f, 0.f);

    float4 wc[4];
    #pragma unroll
    for (int u = 0; u < 4; u++) wc[u] = W4[u * 256 + tid];

    #pragma unroll 1
    for (int k = 0; k < 512; k += 4) {
        float4 wn[4];
        if (k + 4 < 512) {
            #pragma unroll
            for (int u = 0; u < 4; u++) wn[u] = W4[(size_t)(k + 4 + u) * 256 + tid];
        }
        #pragma unroll
        for (int u = 0; u < 4; u++) {
            const float* xr = &s_x[(k + u) * 16];
            float4 xa = *(const float4*)(xr);
            float4 xbv = *(const float4*)(xr + 4);
            float4 xc = *(const float4*)(xr + 8);
            float2 xd = *(const float2*)(xr + 12);
            float2 xp[7];
            xp[0] = make_float2(xa.x, xa.y);  xp[1] = make_float2(xa.z, xa.w);
            xp[2] = make_float2(xbv.x, xbv.y); xp[3] = make_float2(xbv.z, xbv.w);
            xp[4] = make_float2(xc.x, xc.y);  xp[5] = make_float2(xc.z, xc.w);
            xp[6] = xd;
            float2 s0 = make_float2(wc[u].x, wc[u].x);
            float2 s1 = make_float2(wc[u].y, wc[u].y);
            float2 s2 = make_float2(wc[u].z, wc[u].z);
            float2 s3 = make_float2(wc[u].w, wc[u].w);
            #pragma unroll
            for (int p = 0; p < 7; p++) {
                acc[p][0] = ffma2(xp[p], s0, acc[p][0]);
                acc[p][1] = ffma2(xp[p], s1, acc[p][1]);
                acc[p][2] = ffma2(xp[p], s2, acc[p][2]);
                acc[p][3] = ffma2(xp[p], s3, acc[p][3]);
            }
        }
        #pragma unroll
        for (int u = 0; u < 4; u++) wc[u] = wn[u];
    }

    float* dst = g_whp[kh] + (size_t)hb * 14336;
    #pragma unroll
    for (int p = 0; p < 7; p++) {
        *(float4*)&dst[(2 * p) * 1024 + c0] =
            make_float4(acc[p][0].x, acc[p][1].x, acc[p][2].x, acc[p][3].x);
        *(float4*)&dst[(2 * p + 1) * 1024 + c0] =
            make_float4(acc[p][0].y, acc[p][1].y, acc[p][2].y, acc[p][3].y);
    }
}

// ---------------------------------------------------------------------------
// k1b: grid 128 (hb), 256 threads. Sum partials -> Wh regs; a-dots + block
// reduce; masked softmax; h_prime = att @ Wh; write g_hp.
// ---------------------------------------------------------------------------
__global__ __launch_bounds__(256, 1) void k1b(
    const float* __restrict__ adj, const float* __restrict__ a)
{
    __shared__ float s_red[8][28];
    __shared__ float s_dot[28];
    __shared__ float s_att[14 * 16];

    const int tid = threadIdx.x;
    const int hb  = blockIdx.x;
    const int b   = hb & 31;
    const int c0  = tid * 4;
    const int wid = tid >> 5, lane = tid & 31;

    // Wh[n][c0..c0+3] = part0 + part1
    float4 wh[14];
    const float* p0 = g_whp[0] + (size_t)hb * 14336 + c0;
    const float* p1 = g_whp[1] + (size_t)hb * 14336 + c0;
    #pragma unroll
    for (int n = 0; n < 14; n++) {
        float4 v0 = *(const float4*)(p0 + n * 1024);
        float4 v1 = *(const float4*)(p1 + n * 1024);
        wh[n] = make_float4(v0.x + v1.x, v0.y + v1.y, v0.z + v1.z, v0.w + v1.w);
    }

    // partial dots with a1/a2
    float4 a1 = *(const float4*)(a + (size_t)hb * 2048 + c0);
    float4 a2 = *(const float4*)(a + (size_t)hb * 2048 + 1024 + c0);
    float s1[14], s2[14];
    #pragma unroll
    for (int n = 0; n < 14; n++) {
        s1[n] = wh[n].x * a1.x + wh[n].y * a1.y + wh[n].z * a1.z + wh[n].w * a1.w;
        s2[n] = wh[n].x * a2.x + wh[n].y * a2.y + wh[n].z * a2.z + wh[n].w * a2.w;
    }
    #pragma unroll
    for (int n = 0; n < 14; n++) {
        #pragma unroll
        for (int off = 16; off > 0; off >>= 1) {
            s1[n] += __shfl_down_sync(0xFFFFFFFFu, s1[n], off);
            s2[n] += __shfl_down_sync(0xFFFFFFFFu, s2[n], off);
        }
    }
    if (lane == 0) {
        #pragma unroll
        for (int n = 0; n < 14; n++) { s_red[wid][n] = s1[n]; s_red[wid][14 + n] = s2[n]; }
    }
    __syncthreads();
    if (tid < 28) {
        float s = 0.f;
        #pragma unroll
        for (int w = 0; w < 8; w++) s += s_red[w][tid];
        s_dot[tid] = s;
    }
    __syncthreads();

    // e + mask -> s_att[m*16+n]
    if (tid < 196) {
        int n = tid / 14, m = tid - n * 14;
        float e = s_dot[n] + s_dot[14 + m];
        e = (e > 0.f) ? e : 0.2f * e;
        float ad = adj[b * 196 + n * 14 + m];
        s_att[m * 16 + n] = (ad > 0.f) ? e : NEGC;
    }
    __syncthreads();

    // softmax over n for each m
    if (tid < 14) {
        const int m = tid;
        float mx = -3.4e38f, ev[14], s = 0.f;
        #pragma unroll
        for (int n = 0; n < 14; n++) mx = fmaxf(mx, s_att[m * 16 + n]);
        #pragma unroll
        for (int n = 0; n < 14; n++) { ev[n] = expf(s_att[m * 16 + n] - mx); s += ev[n]; }
        float inv = 1.f / s;
        #pragma unroll
        for (int n = 0; n < 14; n++) s_att[m * 16 + n] = ev[n] * inv;
    }
    __syncthreads();

    // h_prime: hp[n][c] = sum_m att[n][m] * Wh[m][c]
    float2 hp[7][4];
    #pragma unroll
    for (int p = 0; p < 7; p++)
        #pragma unroll
        for (int c = 0; c < 4; c++) hp[p][c] = make_float2(0.f, 0.f);

    #pragma unroll
    for (int m = 0; m < 14; m++) {
        float2 t0 = make_float2(wh[m].x, wh[m].x);
        float2 t1 = make_float2(wh[m].y, wh[m].y);
        float2 t2 = make_float2(wh[m].z, wh[m].z);
        float2 t3 = make_float2(wh[m].w, wh[m].w);
        #pragma unroll
        for (int p = 0; p < 7; p++) {
            float2 at = *(const float2*)&s_att[m * 16 + 2 * p];
            hp[p][0] = ffma2(at, t0, hp[p][0]);
            hp[p][1] = ffma2(at, t1, hp[p][1]);
            hp[p][2] = ffma2(at, t2, hp[p][2]);
            hp[p][3] = ffma2(at, t3, hp[p][3]);
        }
    }
    float* hpg = g_hp + (size_t)hb * 14336;
    #pragma unroll
    for (int p = 0; p < 7; p++) {
        *(float4*)&hpg[(2 * p) * 1024 + c0] =
            make_float4(hp[p][0].x, hp[p][1].x, hp[p][2].x, hp[p][3].x);
        *(float4*)&hpg[(2 * p + 1) * 1024 + c0] =
            make_float4(hp[p][0].y, hp[p][1].y, hp[p][2].y, hp[p][3].y);
    }
}

// ---------------------------------------------------------------------------
// k2: smem-tiled GEMM. C[256 o x 32 b] per CTA, k-split 16 (896 each).
// grid (64, 4): bx -> (ks = bx>>2, ot = bx&3), by = h. 256 threads.
// thread: 4 o-pairs (o = obase + 2*to + 64q) x 4 b.
// ---------------------------------------------------------------------------
__global__ __launch_bounds__(256, 2) void k2(const float* __restrict__ fcw)
{
    __shared__ float s_w[32 * 256];             // [k][o]
    __shared__ float s_hp[32 * 32];             // [k][b]

    const int tid = threadIdx.x;
    const int ks  = blockIdx.x >> 2;
    const int ot  = blockIdx.x & 3;
    const int h   = blockIdx.y;
    const int obase = ot * 256;
    const int kbase = ks * 896;

    const int to = tid & 31;                    // o lane
    const int b0 = (tid >> 5) * 4;              // warp-uniform b

    // staging assignments
    const float* wrow = fcw + ((size_t)(h * 1024 + obase + tid)) * 14336 + kbase;
    const int hb_row = tid >> 3;                // 0..31
    const int kk0 = (tid & 7) * 4;
    const float* hprow = g_hp + ((size_t)(h * 32 + hb_row)) * 14336 + kbase + kk0;

    float2 acc[4][4];
    #pragma unroll
    for (int q = 0; q < 4; q++)
        #pragma unroll
        for (int j = 0; j < 4; j++) acc[q][j] = make_float2(0.f, 0.f);

    // preload chunk 0
    float4 vw[8]; float4 vhp;
    #pragma unroll
    for (int q = 0; q < 8; q++) vw[q] = *(const float4*)(wrow + q * 4);
    vhp = *(const float4*)(hprow);

    #pragma unroll 1
    for (int ck = 0; ck < 28; ck++) {
        __syncthreads();
        #pragma unroll
        for (int q = 0; q < 8; q++) {
            s_w[(4 * q + 0) * 256 + tid] = vw[q].x;
            s_w[(4 * q + 1) * 256 + tid] = vw[q].y;
            s_w[(4 * q + 2) * 256 + tid] = vw[q].z;
            s_w[(4 * q + 3) * 256 + tid] = vw[q].w;
        }
        s_hp[(kk0 + 0) * 32 + hb_row] = vhp.x;
        s_hp[(kk0 + 1) * 32 + hb_row] = vhp.y;
        s_hp[(kk0 + 2) * 32 + hb_row] = vhp.z;
        s_hp[(kk0 + 3) * 32 + hb_row] = vhp.w;
        __syncthreads();

        if (ck + 1 < 28) {
            const float* wn = wrow + (ck + 1) * 32;
            #pragma unroll
            for (int q = 0; q < 8; q++) vw[q] = *(const float4*)(wn + q * 4);
            vhp = *(const float4*)(hprow + (ck + 1) * 32);
        }

        #pragma unroll 8
        for (int k = 0; k < 32; k++) {
            float2 af[4];
            #pragma unroll
            for (int q = 0; q < 4; q++)
                af[q] = *(const float2*)&s_w[k * 256 + 2 * to + 64 * q];
            float4 bf = *(const float4*)&s_hp[k * 32 + b0];
            float2 d0 = make_float2(bf.x, bf.x);
            float2 d1 = make_float2(bf.y, bf.y);
            float2 d2 = make_float2(bf.z, bf.z);
            float2 d3 = make_float2(bf.w, bf.w);
            #pragma unroll
            for (int q = 0; q < 4; q++) {
                acc[q][0] = ffma2(af[q], d0, acc[q][0]);
                acc[q][1] = ffma2(af[q], d1, acc[q][1]);
                acc[q][2] = ffma2(af[q], d2, acc[q][2]);
                acc[q][3] = ffma2(af[q], d3, acc[q][3]);
            }
        }
    }

    float* dst = g_part + ((size_t)(h * 16 + ks)) * 32768;
    #pragma unroll
    for (int j = 0; j < 4; j++)
        #pragma unroll
        for (int q = 0; q < 4; q++)
            *(float2*)(dst + (size_t)(b0 + j) * 1024 + obase + 2 * to + 64 * q) = acc[q][j];
}

// ---------------------------------------------------------------------------
// k3: reduce 64 partials + fc_b, log_softmax over OUT_F per b.
// ---------------------------------------------------------------------------
__global__ __launch_bounds__(256, 1) void k3(const float* __restrict__ fcb,
                                             float* __restrict__ out)
{
    __shared__ float red[256];
    const int b = blockIdx.x, tid = threadIdx.x;

    float v[4];
    #pragma unroll
    for (int j = 0; j < 4; j++) {
        int o = tid + j * 256;
        float s = 0.f;
        #pragma unroll 4
        for (int pb = 0; pb < 64; pb++)
            s += g_part[(size_t)pb * 32768 + b * 1024 + o];
        #pragma unroll
        for (int hh = 0; hh < 4; hh++) s += fcb[hh * 1024 + o];
        v[j] = s;
    }

    float mx = fmaxf(fmaxf(v[0], v[1]), fmaxf(v[2], v[3]));
    red[tid] = mx; __syncthreads();
    for (int st = 128; st > 0; st >>= 1) {
        if (tid < st) red[tid] = fmaxf(red[tid], red[tid + st]);
        __syncthreads();
    }
    mx = red[0]; __syncthreads();

    float s = 0.f;
    #pragma unroll
    for (int j = 0; j < 4; j++) s += expf(v[j] - mx);
    red[tid] = s; __syncthreads();
    for (int st = 128; st > 0; st >>= 1) {
        if (tid < st) red[tid] += red[tid + st];
        __syncthreads();
    }
    float lse = mx + logf(red[0]);

    #pragma unroll
    for (int j = 0; j < 4; j++)
        out[b * 1024 + tid + j * 256] = v[j] - lse;
}

// ---------------------------------------------------------------------------
extern "C" void kernel_launch(void* const* d_in, const int* in_sizes, int n_in,
                              void* d_out, int out_size)
{
    const float *x = nullptr, *adj = nullptr, *W = nullptr, *a = nullptr,
                *fcw = nullptr, *fcb = nullptr;
    for (int i = 0; i < n_in; i++) {
        switch (in_sizes[i]) {
            case 32 * 14 * 1024:        x   = (const float*)d_in[i]; break;
            case 32 * 14 * 14:          adj = (const float*)d_in[i]; break;
            case 4 * 32 * 1024 * 1024:  W   = (const float*)d_in[i]; break;
            case 4 * 32 * 2048:         a   = (const float*)d_in[i]; break;
            case 4 * 1024 * 14336:      fcw = (const float*)d_in[i]; break;
            case 4 * 1024:              fcb = (const float*)d_in[i]; break;
            default: break;
        }
    }
    float* out = (float*)d_out;

    k1<<<256, 256>>>(x, W);
    k1b<<<128, 256>>>(adj, a);
    k2<<<dim3(64, 4), 256>>>(fcw);
    k3<<<32, 256>>>(fcb, out);
}

// round 6
// speedup vs baseline: 1.1621x; 1.0658x over previous
#include <cuda_runtime.h>

// ---------------------------------------------------------------------------
// GAT, B=32 N=14 IN=OUT=1024 H=4.
//  k1 : Wh = x@W. One CTA per (hb, col-half). Full K per CTA, no partials.
//  k1b: a-dots + masked softmax + h_prime = att@Wh          -> g_hp
//  k2 : out partials = h_prime @ fc_w^T, double-buffered smem GEMM.
//  k3a: reduce 64 partials + bias (256 CTAs)                -> g_red
//  k3b: log_softmax per b                                   -> d_out
// ---------------------------------------------------------------------------

#define NEGC -9e15f

__device__ __forceinline__ float2 ffma2(float2 a, float2 b, float2 c) {
    float2 d;
    asm("fma.rn.f32x2 %0, %1, %2, %3;"
        : "=l"(*reinterpret_cast<unsigned long long*>(&d))
        : "l"(*reinterpret_cast<unsigned long long*>(&a)),
          "l"(*reinterpret_cast<unsigned long long*>(&b)),
          "l"(*reinterpret_cast<unsigned long long*>(&c)));
    return d;
}

// scratch
__device__ float g_wh[128 * 14 * 1024];        // Wh      (hb, n, c) 7.34MB
__device__ float g_hp[128 * 14 * 1024];        // h_prime (hb, n, c) 7.34MB
__device__ float g_part[64 * 32 * 1024];       // out partials (h*16+ks, b, o)
__device__ float g_red[32 * 1024];             // reduced logits

// ---------------------------------------------------------------------------
// k1: grid 256 = (hb 128) x (col-half 2). 256 threads, thread owns 2 cols,
// full K=1024. dyn smem 64KB: x transposed [k*16 + n].
// ---------------------------------------------------------------------------
__global__ __launch_bounds__(256, 2) void k1(
    const float* __restrict__ x, const float* __restrict__ W)
{
    extern __shared__ float s_x[];              // [k*16 + n], 65536 B

    const int tid = threadIdx.x;
    const int hb  = blockIdx.x >> 1;
    const int ch  = blockIdx.x & 1;
    const int b   = hb & 31;
    const int c0  = ch * 512 + tid * 2;

    // stage x[b] transposed
    const float* xb = x + (size_t)b * 14336;
    for (int idx = tid; idx < 14336; idx += 256) {
        int n = idx >> 10, k = idx & 1023;
        s_x[k * 16 + n] = xb[idx];
    }
    __syncthreads();

    const float* Wp = W + ((size_t)hb << 20) + c0;

    float2 acc[7][2];
    #pragma unroll
    for (int p = 0; p < 7; p++) {
        acc[p][0] = make_float2(0.f, 0.f);
        acc[p][1] = make_float2(0.f, 0.f);
    }

    float2 wc[8];
    #pragma unroll
    for (int u = 0; u < 8; u++)
        wc[u] = *(const float2*)(Wp + (size_t)u * 1024);

    #pragma unroll 1
    for (int k0 = 0; k0 < 1024; k0 += 8) {
        float2 wn[8];
        if (k0 + 8 < 1024) {
            #pragma unroll
            for (int u = 0; u < 8; u++)
                wn[u] = *(const float2*)(Wp + (size_t)(k0 + 8 + u) * 1024);
        }
        #pragma unroll
        for (int u = 0; u < 8; u++) {
            const float* xr = &s_x[(k0 + u) * 16];
            float4 xa = *(const float4*)(xr);
            float4 xb4 = *(const float4*)(xr + 4);
            float4 xc = *(const float4*)(xr + 8);
            float2 xd = *(const float2*)(xr + 12);
            float2 xp[7];
            xp[0] = make_float2(xa.x, xa.y);  xp[1] = make_float2(xa.z, xa.w);
            xp[2] = make_float2(xb4.x, xb4.y); xp[3] = make_float2(xb4.z, xb4.w);
            xp[4] = make_float2(xc.x, xc.y);  xp[5] = make_float2(xc.z, xc.w);
            xp[6] = xd;
            float2 s0 = make_float2(wc[u].x, wc[u].x);
            float2 s1 = make_float2(wc[u].y, wc[u].y);
            #pragma unroll
            for (int p = 0; p < 7; p++) {
                acc[p][0] = ffma2(xp[p], s0, acc[p][0]);
                acc[p][1] = ffma2(xp[p], s1, acc[p][1]);
            }
        }
        #pragma unroll
        for (int u = 0; u < 8; u++) wc[u] = wn[u];
    }

    float* dst = g_wh + (size_t)hb * 14336 + c0;
    #pragma unroll
    for (int p = 0; p < 7; p++) {
        *(float2*)(dst + (size_t)(2 * p) * 1024)     = make_float2(acc[p][0].x, acc[p][1].x);
        *(float2*)(dst + (size_t)(2 * p + 1) * 1024) = make_float2(acc[p][0].y, acc[p][1].y);
    }
}

// ---------------------------------------------------------------------------
// k1b: grid 128 (hb), 256 threads. a-dots + block reduce; masked softmax;
// h_prime = att @ Wh; write g_hp.
// ---------------------------------------------------------------------------
__global__ __launch_bounds__(256, 1) void k1b(
    const float* __restrict__ adj, const float* __restrict__ a)
{
    __shared__ float s_red[8][28];
    __shared__ float s_dot[28];
    __shared__ float s_att[14 * 16];

    const int tid = threadIdx.x;
    const int hb  = blockIdx.x;
    const int b   = hb & 31;
    const int c0  = tid * 4;
    const int wid = tid >> 5, lane = tid & 31;

    float4 wh[14];
    const float* p0 = g_wh + (size_t)hb * 14336 + c0;
    #pragma unroll
    for (int n = 0; n < 14; n++)
        wh[n] = *(const float4*)(p0 + n * 1024);

    float4 a1 = *(const float4*)(a + (size_t)hb * 2048 + c0);
    float4 a2 = *(const float4*)(a + (size_t)hb * 2048 + 1024 + c0);
    float s1[14], s2[14];
    #pragma unroll
    for (int n = 0; n < 14; n++) {
        s1[n] = wh[n].x * a1.x + wh[n].y * a1.y + wh[n].z * a1.z + wh[n].w * a1.w;
        s2[n] = wh[n].x * a2.x + wh[n].y * a2.y + wh[n].z * a2.z + wh[n].w * a2.w;
    }
    #pragma unroll
    for (int n = 0; n < 14; n++) {
        #pragma unroll
        for (int off = 16; off > 0; off >>= 1) {
            s1[n] += __shfl_down_sync(0xFFFFFFFFu, s1[n], off);
            s2[n] += __shfl_down_sync(0xFFFFFFFFu, s2[n], off);
        }
    }
    if (lane == 0) {
        #pragma unroll
        for (int n = 0; n < 14; n++) { s_red[wid][n] = s1[n]; s_red[wid][14 + n] = s2[n]; }
    }
    __syncthreads();
    if (tid < 28) {
        float s = 0.f;
        #pragma unroll
        for (int w = 0; w < 8; w++) s += s_red[w][tid];
        s_dot[tid] = s;
    }
    __syncthreads();

    if (tid < 196) {
        int n = tid / 14, m = tid - n * 14;
        float e = s_dot[n] + s_dot[14 + m];
        e = (e > 0.f) ? e : 0.2f * e;
        float ad = adj[b * 196 + n * 14 + m];
        s_att[m * 16 + n] = (ad > 0.f) ? e : NEGC;
    }
    __syncthreads();

    if (tid < 14) {
        const int m = tid;
        float mx = -3.4e38f, ev[14], s = 0.f;
        #pragma unroll
        for (int n = 0; n < 14; n++) mx = fmaxf(mx, s_att[m * 16 + n]);
        #pragma unroll
        for (int n = 0; n < 14; n++) { ev[n] = expf(s_att[m * 16 + n] - mx); s += ev[n]; }
        float inv = 1.f / s;
        #pragma unroll
        for (int n = 0; n < 14; n++) s_att[m * 16 + n] = ev[n] * inv;
    }
    __syncthreads();

    float2 hp[7][4];
    #pragma unroll
    for (int p = 0; p < 7; p++)
        #pragma unroll
        for (int c = 0; c < 4; c++) hp[p][c] = make_float2(0.f, 0.f);

    #pragma unroll
    for (int m = 0; m < 14; m++) {
        float2 t0 = make_float2(wh[m].x, wh[m].x);
        float2 t1 = make_float2(wh[m].y, wh[m].y);
        float2 t2 = make_float2(wh[m].z, wh[m].z);
        float2 t3 = make_float2(wh[m].w, wh[m].w);
        #pragma unroll
        for (int p = 0; p < 7; p++) {
            float2 at = *(const float2*)&s_att[m * 16 + 2 * p];
            hp[p][0] = ffma2(at, t0, hp[p][0]);
            hp[p][1] = ffma2(at, t1, hp[p][1]);
            hp[p][2] = ffma2(at, t2, hp[p][2]);
            hp[p][3] = ffma2(at, t3, hp[p][3]);
        }
    }
    float* hpg = g_hp + (size_t)hb * 14336;
    #pragma unroll
    for (int p = 0; p < 7; p++) {
        *(float4*)&hpg[(2 * p) * 1024 + c0] =
            make_float4(hp[p][0].x, hp[p][1].x, hp[p][2].x, hp[p][3].x);
        *(float4*)&hpg[(2 * p + 1) * 1024 + c0] =
            make_float4(hp[p][0].y, hp[p][1].y, hp[p][2].y, hp[p][3].y);
    }
}

// ---------------------------------------------------------------------------
// k2: double-buffered smem GEMM. C[256 o x 32 b] per CTA, k-split 16.
// grid (64, 4). One barrier per k-chunk.
// ---------------------------------------------------------------------------
__global__ __launch_bounds__(256, 2) void k2(const float* __restrict__ fcw)
{
    __shared__ float s_w[2][32 * 256];          // [buf][k][o]
    __shared__ float s_hp[2][32 * 32];          // [buf][k][b]

    const int tid = threadIdx.x;
    const int ks  = blockIdx.x >> 2;
    const int ot  = blockIdx.x & 3;
    const int h   = blockIdx.y;
    const int obase = ot * 256;
    const int kbase = ks * 896;

    const int to = tid & 31;
    const int b0 = (tid >> 5) * 4;

    const float* wrow = fcw + ((size_t)(h * 1024 + obase + tid)) * 14336 + kbase;
    const int hb_row = tid >> 3;
    const int kk0 = (tid & 7) * 4;
    const float* hprow = g_hp + ((size_t)(h * 32 + hb_row)) * 14336 + kbase + kk0;

    float2 acc[4][4];
    #pragma unroll
    for (int q = 0; q < 4; q++)
        #pragma unroll
        for (int j = 0; j < 4; j++) acc[q][j] = make_float2(0.f, 0.f);

    // prologue: stage chunk 0 into buffer 0
    {
        float4 vw[8];
        #pragma unroll
        for (int q = 0; q < 8; q++) vw[q] = *(const float4*)(wrow + q * 4);
        float4 vhp = *(const float4*)(hprow);
        #pragma unroll
        for (int q = 0; q < 8; q++) {
            s_w[0][(4 * q + 0) * 256 + tid] = vw[q].x;
            s_w[0][(4 * q + 1) * 256 + tid] = vw[q].y;
            s_w[0][(4 * q + 2) * 256 + tid] = vw[q].z;
            s_w[0][(4 * q + 3) * 256 + tid] = vw[q].w;
        }
        s_hp[0][(kk0 + 0) * 32 + hb_row] = vhp.x;
        s_hp[0][(kk0 + 1) * 32 + hb_row] = vhp.y;
        s_hp[0][(kk0 + 2) * 32 + hb_row] = vhp.z;
        s_hp[0][(kk0 + 3) * 32 + hb_row] = vhp.w;
    }
    __syncthreads();

    #pragma unroll 1
    for (int ck = 0; ck < 28; ck++) {
        const int buf = ck & 1;

        float4 vw[8]; float4 vhp;
        if (ck + 1 < 28) {
            const float* wn = wrow + (ck + 1) * 32;
            #pragma unroll
            for (int q = 0; q < 8; q++) vw[q] = *(const float4*)(wn + q * 4);
            vhp = *(const float4*)(hprow + (ck + 1) * 32);
        }

        #pragma unroll 8
        for (int k = 0; k < 32; k++) {
            float2 af[4];
            #pragma unroll
            for (int q = 0; q < 4; q++)
                af[q] = *(const float2*)&s_w[buf][k * 256 + 2 * to + 64 * q];
            float4 bf = *(const float4*)&s_hp[buf][k * 32 + b0];
            float2 d0 = make_float2(bf.x, bf.x);
            float2 d1 = make_float2(bf.y, bf.y);
            float2 d2 = make_float2(bf.z, bf.z);
            float2 d3 = make_float2(bf.w, bf.w);
            #pragma unroll
            for (int q = 0; q < 4; q++) {
                acc[q][0] = ffma2(af[q], d0, acc[q][0]);
                acc[q][1] = ffma2(af[q], d1, acc[q][1]);
                acc[q][2] = ffma2(af[q], d2, acc[q][2]);
                acc[q][3] = ffma2(af[q], d3, acc[q][3]);
            }
        }

        if (ck + 1 < 28) {
            const int nb = buf ^ 1;
            #pragma unroll
            for (int q = 0; q < 8; q++) {
                s_w[nb][(4 * q + 0) * 256 + tid] = vw[q].x;
                s_w[nb][(4 * q + 1) * 256 + tid] = vw[q].y;
                s_w[nb][(4 * q + 2) * 256 + tid] = vw[q].z;
                s_w[nb][(4 * q + 3) * 256 + tid] = vw[q].w;
            }
            s_hp[nb][(kk0 + 0) * 32 + hb_row] = vhp.x;
            s_hp[nb][(kk0 + 1) * 32 + hb_row] = vhp.y;
            s_hp[nb][(kk0 + 2) * 32 + hb_row] = vhp.z;
            s_hp[nb][(kk0 + 3) * 32 + hb_row] = vhp.w;
            __syncthreads();
        }
    }

    float* dst = g_part + ((size_t)(h * 16 + ks)) * 32768;
    #pragma unroll
    for (int j = 0; j < 4; j++)
        #pragma unroll
        for (int q = 0; q < 4; q++)
            *(float2*)(dst + (size_t)(b0 + j) * 1024 + obase + 2 * to + 64 * q) = acc[q][j];
}

// ---------------------------------------------------------------------------
// k3a: reduce 64 partials + bias. grid 256 (= b*8 + oc), 128 threads.
// ---------------------------------------------------------------------------
__global__ __launch_bounds__(128, 8) void k3a(const float* __restrict__ fcb)
{
    const int b  = blockIdx.x >> 3;
    const int o  = (blockIdx.x & 7) * 128 + threadIdx.x;

    float s = 0.f;
    #pragma unroll 8
    for (int pb = 0; pb < 64; pb++)
        s += g_part[(size_t)pb * 32768 + b * 1024 + o];
    #pragma unroll
    for (int hh = 0; hh < 4; hh++) s += fcb[hh * 1024 + o];
    g_red[b * 1024 + o] = s;
}

// ---------------------------------------------------------------------------
// k3b: log_softmax per b. grid 32, 256 threads.
// ---------------------------------------------------------------------------
__global__ __launch_bounds__(256, 1) void k3b(float* __restrict__ out)
{
    __shared__ float red[256];
    const int b = blockIdx.x, tid = threadIdx.x;

    float4 v = *(const float4*)&g_red[b * 1024 + tid * 4];

    float mx = fmaxf(fmaxf(v.x, v.y), fmaxf(v.z, v.w));
    red[tid] = mx; __syncthreads();
    for (int st = 128; st > 0; st >>= 1) {
        if (tid < st) red[tid] = fmaxf(red[tid], red[tid + st]);
        __syncthreads();
    }
    mx = red[0]; __syncthreads();

    float s = expf(v.x - mx) + expf(v.y - mx) + expf(v.z - mx) + expf(v.w - mx);
    red[tid] = s; __syncthreads();
    for (int st = 128; st > 0; st >>= 1) {
        if (tid < st) red[tid] += red[tid + st];
        __syncthreads();
    }
    float lse = mx + logf(red[0]);

    *(float4*)&out[b * 1024 + tid * 4] =
        make_float4(v.x - lse, v.y - lse, v.z - lse, v.w - lse);
}

// ---------------------------------------------------------------------------
extern "C" void kernel_launch(void* const* d_in, const int* in_sizes, int n_in,
                              void* d_out, int out_size)
{
    const float *x = nullptr, *adj = nullptr, *W = nullptr, *a = nullptr,
                *fcw = nullptr, *fcb = nullptr;
    for (int i = 0; i < n_in; i++) {
        switch (in_sizes[i]) {
            case 32 * 14 * 1024:        x   = (const float*)d_in[i]; break;
            case 32 * 14 * 14:          adj = (const float*)d_in[i]; break;
            case 4 * 32 * 1024 * 1024:  W   = (const float*)d_in[i]; break;
            case 4 * 32 * 2048:         a   = (const float*)d_in[i]; break;
            case 4 * 1024 * 14336:      fcw = (const float*)d_in[i]; break;
            case 4 * 1024:              fcb = (const float*)d_in[i]; break;
            default: break;
        }
    }
    float* out = (float*)d_out;

    cudaFuncSetAttribute(k1, cudaFuncAttributeMaxDynamicSharedMemorySize, 65536);

    k1<<<256, 256, 65536>>>(x, W);
    k1b<<<128, 256>>>(adj, a);
    k2<<<dim3(64, 4), 256>>>(fcw);
    k3a<<<256, 128>>>(fcb);
    k3b<<<32, 256>>>(out);
}